// round 6
// baseline (speedup 1.0000x reference)
#include <cuda_runtime.h>
#include <cstddef>

#define BATCH 2
#define SEQ 2048
#define DMODEL 1024
#define NH 16
#define DKH 64
#define MROWS (BATCH*SEQ)                       // 4096
#define OUT_ELEMS ((size_t)BATCH*SEQ*DMODEL)    // 4,194,304
#define ATTN_ELEMS ((size_t)BATCH*NH*SEQ*SEQ)   // 134,217,728

// Scratch (allocation-free rule: __device__ globals)
__device__ float g_qh[BATCH*NH*SEQ*DKH];
__device__ float g_kh[BATCH*NH*SEQ*DKH];
__device__ float g_vh[BATCH*NH*SEQ*DKH];
__device__ float g_ctx[BATCH*SEQ*DMODEL];
__device__ float g_attn_scratch[ATTN_ELEMS];    // used only if harness out lacks attention

// ---------------------------------------------------------------------------
// NT GEMM, 128x128 tile, 8x8 per thread, 256 threads, double-buffered smem.
// C[m,n] = sum_k A[m,k]*W[n,k] + bias[n]
// MODE 0: scatter to per-head layout (B,H,S,Dk). MODE 1: plain row-major.
// ---------------------------------------------------------------------------
template<int MODE>
__global__ void __launch_bounds__(256) nt_gemm128(const float* __restrict__ A,
                                                  const float* __restrict__ W,
                                                  const float* __restrict__ bias,
                                                  float* __restrict__ out,
                                                  int N, int K)
{
    __shared__ __align__(16) float As[2][8][128];
    __shared__ __align__(16) float Ws[2][8][128];
    const int tid = threadIdx.x;
    const int m0 = blockIdx.y * 128, n0 = blockIdx.x * 128;
    const int lr = tid >> 1;            // 0..127
    const int lc = (tid & 1) * 4;       // 0 or 4
    const int tx = tid & 15, ty = tid >> 4;

    const float* Arow = &A[(size_t)(m0 + lr) * K + lc];
    const float* Wrow = &W[(size_t)(n0 + lr) * K + lc];

    float acc[8][8] = {};

    // preload k-tile 0 into buffer 0
    {
        float4 av = *(const float4*)&Arow[0];
        float4 wv = *(const float4*)&Wrow[0];
        As[0][lc+0][lr] = av.x; As[0][lc+1][lr] = av.y;
        As[0][lc+2][lr] = av.z; As[0][lc+3][lr] = av.w;
        Ws[0][lc+0][lr] = wv.x; Ws[0][lc+1][lr] = wv.y;
        Ws[0][lc+2][lr] = wv.z; Ws[0][lc+3][lr] = wv.w;
    }
    __syncthreads();

    int buf = 0;
    for (int k0 = 0; k0 < K; k0 += 8) {
        float4 av2, wv2;
        const bool has_next = (k0 + 8 < K);
        if (has_next) {
            av2 = *(const float4*)&Arow[k0 + 8];
            wv2 = *(const float4*)&Wrow[k0 + 8];
        }
        #pragma unroll
        for (int k = 0; k < 8; k++) {
            float a[8], b[8];
            *(float4*)(a+0) = *(const float4*)&As[buf][k][ty*8+0];
            *(float4*)(a+4) = *(const float4*)&As[buf][k][ty*8+4];
            *(float4*)(b+0) = *(const float4*)&Ws[buf][k][tx*8+0];
            *(float4*)(b+4) = *(const float4*)&Ws[buf][k][tx*8+4];
            #pragma unroll
            for (int i = 0; i < 8; i++)
                #pragma unroll
                for (int j = 0; j < 8; j++)
                    acc[i][j] += a[i] * b[j];
        }
        if (has_next) {
            const int nb = buf ^ 1;
            As[nb][lc+0][lr] = av2.x; As[nb][lc+1][lr] = av2.y;
            As[nb][lc+2][lr] = av2.z; As[nb][lc+3][lr] = av2.w;
            Ws[nb][lc+0][lr] = wv2.x; Ws[nb][lc+1][lr] = wv2.y;
            Ws[nb][lc+2][lr] = wv2.z; Ws[nb][lc+3][lr] = wv2.w;
            __syncthreads();
            buf = nb;
        }
    }

    #pragma unroll
    for (int i = 0; i < 8; i++) {
        int m = m0 + ty*8 + i;
        #pragma unroll
        for (int jj = 0; jj < 2; jj++) {
            int n = n0 + tx*8 + jj*4;
            float4 v;
            v.x = acc[i][jj*4+0] + bias[n+0];
            v.y = acc[i][jj*4+1] + bias[n+1];
            v.z = acc[i][jj*4+2] + bias[n+2];
            v.w = acc[i][jj*4+3] + bias[n+3];
            if (MODE == 0) {
                // n is 4-aligned; head boundary is 64-aligned -> same head for all 4
                int b_ = m / SEQ, s = m % SEQ;
                int h = n / DKH, dk = n % DKH;
                *(float4*)&out[(((size_t)b_ * NH + h) * SEQ + s) * DKH + dk] = v;
            } else {
                *(float4*)&out[(size_t)m * DMODEL + n] = v;
            }
        }
    }
}

// ---------------------------------------------------------------------------
// scores[bh, m, n] = (Q[bh,m,:] . K[bh,n,:]) / 8
// 128x128 tile; K=64 staged as 2 x KTILE=32 (32 KB smem), 4 barriers total.
// ---------------------------------------------------------------------------
__global__ void __launch_bounds__(256) scores_gemm128(float* __restrict__ attn)
{
    const int bh = blockIdx.z;
    const float* A  = g_qh + (size_t)bh * SEQ * DKH;
    const float* Bk = g_kh + (size_t)bh * SEQ * DKH;
    float* C = attn + (size_t)bh * SEQ * SEQ;

    __shared__ __align__(16) float As[32][128];
    __shared__ __align__(16) float Ws[32][128];
    const int tid = threadIdx.x;
    const int m0 = blockIdx.y * 128, n0 = blockIdx.x * 128;
    const int lr = tid >> 1;             // 0..127 row
    const int lc = (tid & 1) * 16;       // col base 0 or 16 (loads 4 float4)
    const int tx = tid & 15, ty = tid >> 4;

    float acc[8][8] = {};

    for (int k0 = 0; k0 < DKH; k0 += 32) {
        #pragma unroll
        for (int i = 0; i < 4; i++) {
            float4 av = *(const float4*)&A [(size_t)(m0 + lr) * DKH + k0 + lc + 4*i];
            float4 wv = *(const float4*)&Bk[(size_t)(n0 + lr) * DKH + k0 + lc + 4*i];
            As[lc+4*i+0][lr] = av.x; As[lc+4*i+1][lr] = av.y;
            As[lc+4*i+2][lr] = av.z; As[lc+4*i+3][lr] = av.w;
            Ws[lc+4*i+0][lr] = wv.x; Ws[lc+4*i+1][lr] = wv.y;
            Ws[lc+4*i+2][lr] = wv.z; Ws[lc+4*i+3][lr] = wv.w;
        }
        __syncthreads();
        #pragma unroll
        for (int k = 0; k < 32; k++) {
            float a[8], b[8];
            *(float4*)(a+0) = *(const float4*)&As[k][ty*8+0];
            *(float4*)(a+4) = *(const float4*)&As[k][ty*8+4];
            *(float4*)(b+0) = *(const float4*)&Ws[k][tx*8+0];
            *(float4*)(b+4) = *(const float4*)&Ws[k][tx*8+4];
            #pragma unroll
            for (int i = 0; i < 8; i++)
                #pragma unroll
                for (int j = 0; j < 8; j++)
                    acc[i][j] += a[i] * b[j];
        }
        __syncthreads();
    }

    #pragma unroll
    for (int i = 0; i < 8; i++) {
        int m = m0 + ty*8 + i;
        #pragma unroll
        for (int jj = 0; jj < 2; jj++) {
            int n = n0 + tx*8 + jj*4;
            float4 v;
            v.x = acc[i][jj*4+0] * 0.125f;
            v.y = acc[i][jj*4+1] * 0.125f;
            v.z = acc[i][jj*4+2] * 0.125f;
            v.w = acc[i][jj*4+3] * 0.125f;
            *(float4*)&C[(size_t)m * SEQ + n] = v;
        }
    }
}

// ---------------------------------------------------------------------------
// Row softmax in place over attn (with mask). One block per row of 2048.
// ---------------------------------------------------------------------------
__global__ void __launch_bounds__(256) softmax_rows(float* __restrict__ attn,
                                                    const int* __restrict__ mask)
{
    const int row = blockIdx.x;                 // 0 .. B*H*S-1
    const int b = row / (NH * SEQ);
    float* p = attn + (size_t)row * SEQ;
    const int* mrow = mask + (size_t)b * SEQ;
    const int tid = threadIdx.x;
    const int lane = tid & 31, warp = tid >> 5;

    float x[8];
    float mx = -1e30f;
    #pragma unroll
    for (int i = 0; i < 8; i++) {
        int j = tid + i * 256;
        float v = p[j];
        if (mrow[j] == 0) v = -1e9f;
        x[i] = v;
        mx = fmaxf(mx, v);
    }
    __shared__ float smax[8], ssum[8];
    #pragma unroll
    for (int o = 16; o; o >>= 1) mx = fmaxf(mx, __shfl_xor_sync(0xffffffffu, mx, o));
    if (lane == 0) smax[warp] = mx;
    __syncthreads();
    float bm = smax[0];
    #pragma unroll
    for (int w = 1; w < 8; w++) bm = fmaxf(bm, smax[w]);

    float s = 0.f;
    #pragma unroll
    for (int i = 0; i < 8; i++) { x[i] = __expf(x[i] - bm); s += x[i]; }
    #pragma unroll
    for (int o = 16; o; o >>= 1) s += __shfl_xor_sync(0xffffffffu, s, o);
    if (lane == 0) ssum[warp] = s;
    __syncthreads();
    float bs = 0.f;
    #pragma unroll
    for (int w = 0; w < 8; w++) bs += ssum[w];
    float inv = 1.0f / bs;

    #pragma unroll
    for (int i = 0; i < 8; i++) p[tid + i * 256] = x[i] * inv;
}

// ---------------------------------------------------------------------------
// ctx[b,s,h,:] = attn[bh,s,:] @ V[bh,:,:]   (NN gemm, K = SEQ, N = DKH = 64)
// 128x64 tile, 8x4 per thread, 256 threads, double-buffered smem.
// ---------------------------------------------------------------------------
__global__ void __launch_bounds__(256) av_gemm128(const float* __restrict__ attn)
{
    const int bh = blockIdx.z;
    const int b = bh / NH, h = bh % NH;
    const float* A  = attn + (size_t)bh * SEQ * SEQ;
    const float* Bv = g_vh + (size_t)bh * SEQ * DKH;

    __shared__ __align__(16) float As[2][16][128];   // k x m
    __shared__ __align__(16) float Bs[2][16][64];    // k x n
    const int tid = threadIdx.x;
    const int tx = tid & 15, ty = tid >> 4;       // tx -> n (4 each), ty -> m (8 each)
    const int m0 = blockIdx.y * 128;

    const int lr  = tid >> 1;            // 0..127 row of A tile
    const int lk4 = (tid & 1) * 8;       // 0 or 8
    const int brow = tid >> 4;           // 0..15
    const int bc   = (tid & 15) * 4;     // 0..60

    const float* Aro = &A[(size_t)(m0 + lr) * SEQ + lk4];
    const float* Bro = &Bv[(size_t)brow * DKH + bc];

    float acc[8][4] = {};

    // preload k-tile 0
    {
        float4 a0 = *(const float4*)&Aro[0];
        float4 a1 = *(const float4*)&Aro[4];
        float4 bv = *(const float4*)&Bro[0];
        As[0][lk4+0][lr] = a0.x; As[0][lk4+1][lr] = a0.y;
        As[0][lk4+2][lr] = a0.z; As[0][lk4+3][lr] = a0.w;
        As[0][lk4+4][lr] = a1.x; As[0][lk4+5][lr] = a1.y;
        As[0][lk4+6][lr] = a1.z; As[0][lk4+7][lr] = a1.w;
        *(float4*)&Bs[0][brow][bc] = bv;
    }
    __syncthreads();

    int buf = 0;
    for (int k0 = 0; k0 < SEQ; k0 += 16) {
        float4 a0n, a1n, bvn;
        const bool has_next = (k0 + 16 < SEQ);
        if (has_next) {
            a0n = *(const float4*)&Aro[k0 + 16];
            a1n = *(const float4*)&Aro[k0 + 20];
            bvn = *(const float4*)&Bro[(size_t)(k0 + 16) * DKH];
        }
        #pragma unroll
        for (int k = 0; k < 16; k++) {
            float a[8], b2[4];
            *(float4*)(a+0) = *(const float4*)&As[buf][k][ty*8+0];
            *(float4*)(a+4) = *(const float4*)&As[buf][k][ty*8+4];
            *(float4*)b2    = *(const float4*)&Bs[buf][k][tx*4];
            #pragma unroll
            for (int i = 0; i < 8; i++)
                #pragma unroll
                for (int j = 0; j < 4; j++)
                    acc[i][j] += a[i] * b2[j];
        }
        if (has_next) {
            const int nb = buf ^ 1;
            As[nb][lk4+0][lr] = a0n.x; As[nb][lk4+1][lr] = a0n.y;
            As[nb][lk4+2][lr] = a0n.z; As[nb][lk4+3][lr] = a0n.w;
            As[nb][lk4+4][lr] = a1n.x; As[nb][lk4+5][lr] = a1n.y;
            As[nb][lk4+6][lr] = a1n.z; As[nb][lk4+7][lr] = a1n.w;
            *(float4*)&Bs[nb][brow][bc] = bvn;
            __syncthreads();
            buf = nb;
        }
    }
    #pragma unroll
    for (int i = 0; i < 8; i++) {
        int s = m0 + ty*8 + i;
        float4 v = make_float4(acc[i][0], acc[i][1], acc[i][2], acc[i][3]);
        int dk = tx * 4;
        *(float4*)&g_ctx[(((size_t)b * SEQ + s) * NH + h) * DKH + dk] = v;
    }
}

// ---------------------------------------------------------------------------
extern "C" void kernel_launch(void* const* d_in, const int* in_sizes, int n_in,
                              void* d_out, int out_size)
{
    const float* q    = (const float*)d_in[0];
    const float* k    = (const float*)d_in[1];
    const float* v    = (const float*)d_in[2];
    const int*   mask = (const int*)  d_in[3];
    const float* wq_w = (const float*)d_in[4];
    const float* wq_b = (const float*)d_in[5];
    const float* wk_w = (const float*)d_in[6];
    const float* wk_b = (const float*)d_in[7];
    const float* wv_w = (const float*)d_in[8];
    const float* wv_b = (const float*)d_in[9];
    const float* wo_w = (const float*)d_in[10];
    const float* wo_b = (const float*)d_in[11];

    float* out = (float*)d_out;

    void *pq, *pk, *pv, *pctx, *pattn_s;
    cudaGetSymbolAddress(&pq,   g_qh);
    cudaGetSymbolAddress(&pk,   g_kh);
    cudaGetSymbolAddress(&pv,   g_vh);
    cudaGetSymbolAddress(&pctx, g_ctx);
    cudaGetSymbolAddress(&pattn_s, g_attn_scratch);

    // Tuple output: out (B*S*D) first, attention (B*H*S*S) second.
    float* attn = ((size_t)out_size >= OUT_ELEMS + ATTN_ELEMS)
                      ? (out + OUT_ELEMS) : (float*)pattn_s;

    dim3 blk(256);
    dim3 gProj(DMODEL / 128, MROWS / 128);         // (8, 32)
    nt_gemm128<0><<<gProj, blk>>>(q, wq_w, wq_b, (float*)pq, DMODEL, DMODEL);
    nt_gemm128<0><<<gProj, blk>>>(k, wk_w, wk_b, (float*)pk, DMODEL, DMODEL);
    nt_gemm128<0><<<gProj, blk>>>(v, wv_w, wv_b, (float*)pv, DMODEL, DMODEL);

    dim3 gSc(SEQ / 128, SEQ / 128, BATCH * NH);    // (16, 16, 32)
    scores_gemm128<<<gSc, blk>>>(attn);

    softmax_rows<<<BATCH * NH * SEQ, blk>>>(attn, mask);

    dim3 gAv(1, SEQ / 128, BATCH * NH);            // (1, 16, 32)
    av_gemm128<<<gAv, blk>>>(attn);

    nt_gemm128<1><<<gProj, blk>>>((const float*)pctx, wo_w, wo_b, out,
                                  DMODEL, DMODEL);
}